// round 4
// baseline (speedup 1.0000x reference)
#include <cuda_runtime.h>
#include <cstdint>

#define BATCH   2048
#define FDIM    512
#define NTREES  512
#define NCOLS   2560
#define TDEPTH  5
#define NLEAF   32

#define BM      128      // batch rows per CTA
#define TB      32       // trees per CTA
#define BN      160      // GEMM N per CTA
#define KC      32       // K per chunk
#define NCHUNK  16       // 512/32
#define NTHR    512      // 16 warps

// W transposed + softmaxed: [NCOLS][FDIM], K-major per column (scratch)
__device__ float g_Wt[NCOLS * FDIM];

// smem map (bytes). Stages: A 128x32 f32 = 16KB, B 160x32 f32 = 20KB. 2 stages.
#define OFF_A0   0
#define OFF_B0   16384
#define OFF_A1   36864
#define OFF_B1   53248
// epilogue D tile reuses [0, 82944): 128 x 162 floats
#define OFF_RESP 82944
#define OFF_THR  87040
#define OFF_IT   87680
#define SMEM_BYTES 88320

// mma.sync m16n8k8 tf32 (raw fp32 bits -> RZ-truncated tf32)
__device__ __forceinline__ void mma8(float* d, uint2 aLo, uint2 aHi, uint2 b) {
    asm volatile(
        "mma.sync.aligned.m16n8k8.row.col.f32.tf32.tf32.f32 "
        "{%0,%1,%2,%3}, {%4,%5,%6,%7}, {%8,%9}, {%0,%1,%2,%3};"
        : "+f"(d[0]), "+f"(d[1]), "+f"(d[2]), "+f"(d[3])
        : "r"(aLo.x), "r"(aHi.x), "r"(aLo.y), "r"(aHi.y), "r"(b.x), "r"(b.y));
}

// ---------------------------------------------------------------------------
// Softmax over feat_attention axis 0 -> transposed g_Wt[n][f].
// Single gmem read: tile [512 f][32 c] cached in smem (stride 33, conflict-
// free both column-wise reductions and transposed f-major reads).
// ---------------------------------------------------------------------------
__global__ void softmax_t_kernel(const float* __restrict__ fa) {
    extern __shared__ float st[];              // [512][33]
    __shared__ float red[8][32];
    __shared__ float s_mx[32], s_inv[32];

    const int tid = threadIdx.x;
    const int lx  = tid & 31;
    const int ry  = tid >> 5;
    const int c0  = blockIdx.x * 32;
    const int c   = c0 + lx;

    #pragma unroll
    for (int r = 0; r < 16; r++) {
        int q = tid + r * 256;
        int f = q >> 3, cq = q & 7;
        float4 v = *(const float4*)&fa[(size_t)f * NCOLS + c0 + cq * 4];
        float* p = &st[f * 33 + cq * 4];
        p[0] = v.x; p[1] = v.y; p[2] = v.z; p[3] = v.w;
    }
    __syncthreads();

    float m = -1e30f;
    for (int f = ry; f < FDIM; f += 8) m = fmaxf(m, st[f * 33 + lx]);
    red[ry][lx] = m;
    __syncthreads();
    if (ry == 0) {
        float mm = red[0][lx];
        #pragma unroll
        for (int r = 1; r < 8; r++) mm = fmaxf(mm, red[r][lx]);
        s_mx[lx] = mm;
    }
    __syncthreads();
    const float mx = s_mx[lx];

    float s = 0.f;
    for (int f = ry; f < FDIM; f += 8) {
        float e = __expf(st[f * 33 + lx] - mx);
        st[f * 33 + lx] = e;                  // cache exp in place
        s += e;
    }
    red[ry][lx] = s;
    __syncthreads();
    if (ry == 0) {
        float t = 0.f;
        #pragma unroll
        for (int r = 0; r < 8; r++) t += red[r][lx];
        s_inv[lx] = 1.0f / t;
    }
    __syncthreads();

    // transposed write: lane = f-quad (fast), tid>>3... use lx-major for banks
    const int fq      = tid & 7;               // f-quad within 32-f group
    const int n_local = tid >> 3;               // column (tree-col) 0..31
    const float inv   = s_inv[n_local];
    for (int f0 = 0; f0 < FDIM; f0 += 32) {
        int f = f0 + fq * 4;
        float4 v;
        v.x = st[(f + 0) * 33 + n_local] * inv;
        v.y = st[(f + 1) * 33 + n_local] * inv;
        v.z = st[(f + 2) * 33 + n_local] * inv;
        v.w = st[(f + 3) * 33 + n_local] * inv;
        *(float4*)&g_Wt[(size_t)(c0 + n_local) * FDIM + f] = v;
    }
}

// ---------------------------------------------------------------------------
// Main: tf32 mma.sync GEMM (128x160x512), 16 warps (4x4), warp tile 32x40.
// Smem rows: 16 float2 pairs, pair (k, k+4) at rotated index -> LDS.64 frags.
// ---------------------------------------------------------------------------
__global__ __launch_bounds__(NTHR, 1)
void detree_mma_kernel(const float* __restrict__ x,
                       const float* __restrict__ thr,
                       const float* __restrict__ logt,
                       const float* __restrict__ resp,
                       float* __restrict__ out) {
    extern __shared__ char sm[];
    float* s_resp = (float*)(sm + OFF_RESP);
    float* s_thr  = (float*)(sm + OFF_THR);
    float* s_it   = (float*)(sm + OFF_IT);
    float* s_D    = (float*)sm;

    const int tid  = threadIdx.x;
    const int wid  = tid >> 5;
    const int lane = tid & 31;
    const int g    = lane >> 2;
    const int tig  = lane & 3;
    const int wm   = wid >> 2;        // 0..3
    const int wn   = wid & 3;         // 0..3
    const int m0    = blockIdx.y * BM;
    const int tree0 = blockIdx.x * TB;
    const int n0    = tree0 * TDEPTH;

    if (tid < 256)
        ((float4*)s_resp)[tid] = ((const float4*)(resp + (size_t)tree0 * NLEAF))[tid];
    if (tid >= 256 && tid < 256 + TB * TDEPTH) {
        int q = tid - 256;
        s_thr[q] = thr[n0 + q];
        s_it[q]  = __expf(-logt[n0 + q]);
    }

    // loader cells: (row, s) ; each cell = 8 consecutive k as 2 float4
    const int rA  = tid >> 2, sA = tid & 3;          // A: 512 cells
    const int rB0 = tid >> 2, sB0 = tid & 3;         // B cells 0..511
    const int rB1 = 128 + (tid >> 2), sB1 = tid & 3; // B cells 512..639
    const bool hasB1 = (tid < 128);

    float4 aLo, aHi, bLo0, bHi0, bLo1, bHi1;

    auto ldg_chunk = [&](int k0) {
        const float* xa = x + (size_t)m0 * FDIM + k0;
        const float* wb = g_Wt + (size_t)n0 * FDIM + k0;
        aLo  = *(const float4*)(xa + (size_t)rA * FDIM + sA * 8);
        aHi  = *(const float4*)(xa + (size_t)rA * FDIM + sA * 8 + 4);
        bLo0 = *(const float4*)(wb + (size_t)rB0 * FDIM + sB0 * 8);
        bHi0 = *(const float4*)(wb + (size_t)rB0 * FDIM + sB0 * 8 + 4);
        if (hasB1) {
            bLo1 = *(const float4*)(wb + (size_t)rB1 * FDIM + sB1 * 8);
            bHi1 = *(const float4*)(wb + (size_t)rB1 * FDIM + sB1 * 8 + 4);
        }
    };

    auto sts_cell = [&](float* base, int r, int s, const float4& lo, const float4& hi) {
        int fb = (s * 4 + 4 * (r & 3)) & 15;
        float* p = base + r * 32 + fb * 2;
        *(float4*)p       = make_float4(lo.x, hi.x, lo.y, hi.y);
        *(float4*)(p + 4) = make_float4(lo.z, hi.z, lo.w, hi.w);
    };

    auto sts_chunk = [&](int st) {
        float* As = (float*)(sm + (st ? OFF_A1 : OFF_A0));
        float* Bs = (float*)(sm + (st ? OFF_B1 : OFF_B0));
        sts_cell(As, rA, sA, aLo, aHi);
        sts_cell(Bs, rB0, sB0, bLo0, bHi0);
        if (hasB1) sts_cell(Bs, rB1, sB1, bLo1, bHi1);
    };

    float d[2][5][4];
    #pragma unroll
    for (int mt = 0; mt < 2; mt++)
        #pragma unroll
        for (int nt = 0; nt < 5; nt++)
            #pragma unroll
            for (int q = 0; q < 4; q++) d[mt][nt][q] = 0.f;

    ldg_chunk(0);
    sts_chunk(0);
    ldg_chunk(KC);
    __syncthreads();

    for (int i = 0; i < NCHUNK; i++) {
        const int st = i & 1;
        if (i + 1 < NCHUNK) sts_chunk(st ^ 1);
        if (i + 2 < NCHUNK) ldg_chunk((i + 2) * KC);

        const uint32_t* As = (const uint32_t*)(sm + (st ? OFF_A1 : OFF_A0));
        const uint32_t* Bs = (const uint32_t*)(sm + (st ? OFF_B1 : OFF_B0));

        #pragma unroll
        for (int s = 0; s < 4; s++) {
            const int fb = ((s * 4 + tig) + 4 * (g & 3)) & 15;
            uint2 afLo[2], afHi[2], bf[5];
            #pragma unroll
            for (int mt = 0; mt < 2; mt++) {
                int row = wm * 32 + mt * 16 + g;
                afLo[mt] = *((const uint2*)(As + row * 32) + fb);
                afHi[mt] = *((const uint2*)(As + (row + 8) * 32) + fb);
            }
            #pragma unroll
            for (int nt = 0; nt < 5; nt++) {
                int row = wn * 40 + nt * 8 + g;
                bf[nt] = *((const uint2*)(Bs + row * 32) + fb);
            }
            #pragma unroll
            for (int mt = 0; mt < 2; mt++)
                #pragma unroll
                for (int nt = 0; nt < 5; nt++)
                    mma8(d[mt][nt], afLo[mt], afHi[mt], bf[nt]);
        }
        __syncthreads();
    }

    // ---- D -> padded smem [128][162] ----
    #pragma unroll
    for (int mt = 0; mt < 2; mt++) {
        const int row0 = wm * 32 + mt * 16 + g;
        #pragma unroll
        for (int nt = 0; nt < 5; nt++) {
            const int col = wn * 40 + nt * 8 + 2 * tig;
            *(float2*)&s_D[row0 * 162 + col]       = make_float2(d[mt][nt][0], d[mt][nt][1]);
            *(float2*)&s_D[(row0 + 8) * 162 + col] = make_float2(d[mt][nt][2], d[mt][nt][3]);
        }
    }
    __syncthreads();

    // ---- tree routing epilogue: 8 (row,tree) pairs per thread ----
    #pragma unroll
    for (int t = 0; t < 8; t++) {
        const int q   = tid + t * NTHR;
        const int row = q >> 5;
        const int tr  = q & 31;

        float c0a[5], c1a[5];
        #pragma unroll
        for (int dd = 0; dd < TDEPTH; dd++) {
            float fv = s_D[row * 162 + tr * 5 + dd];
            float tl = (fv - s_thr[tr * 5 + dd]) * s_it[tr * 5 + dd];
            c1a[dd] = __saturatef(fmaf( 0.5f, tl, 0.5f));
            c0a[dd] = __saturatef(fmaf(-0.5f, tl, 0.5f));
        }
        float p[NLEAF];
        p[0] = c0a[0];
        p[1] = c1a[0];
        #pragma unroll
        for (int jj = 1; jj < TDEPTH; jj++) {
            const int sz = 1 << jj;
            #pragma unroll
            for (int l = 0; l < 16; l++) {
                if (l < sz) {
                    p[l + sz] = p[l] * c1a[jj];
                    p[l]      = p[l] * c0a[jj];
                }
            }
        }
        float ssum = 0.f;
        const float4* r4 = (const float4*)&s_resp[tr * NLEAF];
        #pragma unroll
        for (int qq = 0; qq < 8; qq++) {
            float4 rv = r4[qq];
            ssum = fmaf(p[4 * qq + 0], rv.x, ssum);
            ssum = fmaf(p[4 * qq + 1], rv.y, ssum);
            ssum = fmaf(p[4 * qq + 2], rv.z, ssum);
            ssum = fmaf(p[4 * qq + 3], rv.w, ssum);
        }
        out[(size_t)(m0 + row) * NTREES + tree0 + tr] = ssum;
    }
}

extern "C" void kernel_launch(void* const* d_in, const int* in_sizes, int n_in,
                              void* d_out, int out_size) {
    const float* x    = (const float*)d_in[0];
    const float* fa   = (const float*)d_in[1];
    const float* thr  = (const float*)d_in[2];
    const float* logt = (const float*)d_in[3];
    const float* resp = (const float*)d_in[4];
    float* out = (float*)d_out;

    const int sm_soft = 512 * 33 * 4;
    cudaFuncSetAttribute(softmax_t_kernel,
                         cudaFuncAttributeMaxDynamicSharedMemorySize, sm_soft);
    cudaFuncSetAttribute(detree_mma_kernel,
                         cudaFuncAttributeMaxDynamicSharedMemorySize, SMEM_BYTES);

    softmax_t_kernel<<<NCOLS / 32, 256, sm_soft>>>(fa);
    detree_mma_kernel<<<dim3(NTREES / TB, BATCH / BM), NTHR, SMEM_BYTES>>>(
        x, thr, logt, resp, out);
}

// round 6
// speedup vs baseline: 1.2394x; 1.2394x over previous
#include <cuda_runtime.h>
#include <cstdint>

#define BATCH   2048
#define FDIM    512
#define NTREES  512
#define NCOLS   2560
#define TDEPTH  5
#define NLEAF   32

#define BM      256      // batch rows per CTA
#define TB      32       // trees per CTA
#define BN      160      // GEMM N per CTA
#define KC      32       // K per chunk
#define NCHUNK  16
#define NTHR    512      // 16 warps, 4x4, warp tile 64x40
#define NSTAGE  3

// pre-permuted operands (cell-interleaved, row-rotated)
__device__ float g_Xp[BATCH * FDIM];        // 4 MB
__device__ float g_Wt[NCOLS * FDIM];        // 5 MB

// smem: 3 stages x (A 256x128B = 32KB + B 160x128B = 20KB) then tables
#define STAGE_BYTES 53248
#define OFF_TAB     (NSTAGE * STAGE_BYTES)          // 159744
#define OFF_RESP    OFF_TAB                          // 4096 B
#define OFF_THR     (OFF_TAB + 4096)                 // 640 B
#define OFF_IT      (OFF_TAB + 4736)                 // 640 B
#define SMEM_BYTES  (OFF_TAB + 5376)

// Cell layout: for (row r, s in 0..3) within a 32-float chunk, the 8 floats
// k = s*8+p and s*8+p+4 (p=0..3) are stored interleaved
// [lo.x,hi.x,lo.y,hi.y,lo.z,hi.z,lo.w,hi.w] at float2-index
// fb = (s*4 + 4*(r&3)) & 15 within the 128B row. All tile bases are
// multiples of 4 rows, so global-row rotation == tile-row rotation.

__device__ __forceinline__ uint32_t smem_u32(const void* p) {
    uint32_t a;
    asm("{ .reg .u64 t; cvta.to.shared.u64 t, %1; cvt.u32.u64 %0, t; }"
        : "=r"(a) : "l"(p));
    return a;
}
__device__ __forceinline__ void cpa16(uint32_t dst, const float* src) {
    asm volatile("cp.async.cg.shared.global [%0], [%1], 16;"
                 :: "r"(dst), "l"(src));
}
#define CP_COMMIT() asm volatile("cp.async.commit_group;" ::: "memory")

__device__ __forceinline__ void mma8(float* d, uint2 aLo, uint2 aHi, uint2 b) {
    asm volatile(
        "mma.sync.aligned.m16n8k8.row.col.f32.tf32.tf32.f32 "
        "{%0,%1,%2,%3}, {%4,%5,%6,%7}, {%8,%9}, {%0,%1,%2,%3};"
        : "+f"(d[0]), "+f"(d[1]), "+f"(d[2]), "+f"(d[3])
        : "r"(aLo.x), "r"(aHi.x), "r"(aLo.y), "r"(aHi.y), "r"(b.x), "r"(b.y));
}

// ---------------------------------------------------------------------------
// Permute x -> g_Xp (cell-interleaved). One 8-float cell per thread.
// Total cells = BATCH * FDIM / 8 = 131072 -> 512 blocks x 256 threads.
// ---------------------------------------------------------------------------
__global__ void permute_x_kernel(const float* __restrict__ x) {
    const int id  = blockIdx.x * 256 + threadIdx.x;
    const int row = id >> 6;              // 64 cells per row
    const int c   = (id >> 2) & 15;       // chunk
    const int s   = id & 3;
    const float4 lo = *(const float4*)&x[(size_t)row * FDIM + c * 32 + s * 8];
    const float4 hi = *(const float4*)&x[(size_t)row * FDIM + c * 32 + s * 8 + 4];
    const int fb = (s * 4 + 4 * (row & 3)) & 15;
    float* o = g_Xp + (size_t)row * FDIM + c * 32 + fb * 2;
    *(float4*)o       = make_float4(lo.x, hi.x, lo.y, hi.y);
    *(float4*)(o + 4) = make_float4(lo.z, hi.z, lo.w, hi.w);
}

// ---------------------------------------------------------------------------
// Softmax over feat_attention axis 0 -> transposed + cell-permuted g_Wt[n][.]
// ---------------------------------------------------------------------------
__global__ void softmax_t_kernel(const float* __restrict__ fa) {
    extern __shared__ float st[];              // [512][33]
    __shared__ float red[8][32];
    __shared__ float s_mx[32], s_inv[32];

    const int tid = threadIdx.x;
    const int lx  = tid & 31;
    const int ry  = tid >> 5;
    const int c0  = blockIdx.x * 32;

    #pragma unroll
    for (int r = 0; r < 16; r++) {
        int q = tid + r * 256;
        int f = q >> 3, cq = q & 7;
        float4 v = *(const float4*)&fa[(size_t)f * NCOLS + c0 + cq * 4];
        float* p = &st[f * 33 + cq * 4];
        p[0] = v.x; p[1] = v.y; p[2] = v.z; p[3] = v.w;
    }
    __syncthreads();

    float m = -1e30f;
    for (int f = ry; f < FDIM; f += 8) m = fmaxf(m, st[f * 33 + lx]);
    red[ry][lx] = m;
    __syncthreads();
    if (ry == 0) {
        float mm = red[0][lx];
        #pragma unroll
        for (int r = 1; r < 8; r++) mm = fmaxf(mm, red[r][lx]);
        s_mx[lx] = mm;
    }
    __syncthreads();
    const float mx = s_mx[lx];

    float s = 0.f;
    for (int f = ry; f < FDIM; f += 8) {
        float e = __expf(st[f * 33 + lx] - mx);
        st[f * 33 + lx] = e;
        s += e;
    }
    red[ry][lx] = s;
    __syncthreads();
    if (ry == 0) {
        float t = 0.f;
        #pragma unroll
        for (int r = 0; r < 8; r++) t += red[r][lx];
        s_inv[lx] = 1.0f / t;
    }
    __syncthreads();

    const int fq      = tid & 7;
    const int n_local = tid >> 3;
    const int n       = c0 + n_local;
    const float inv   = s_inv[n_local];
    const int rot4    = 4 * (n_local & 3);

    #pragma unroll
    for (int j = 0; j < 2; j++) {
        const int c = fq + j * 8;              // chunk
        #pragma unroll
        for (int sstep = 0; sstep < 4; sstep++) {
            const int kb = c * 32 + sstep * 8;
            float lo[4], hi[4];
            #pragma unroll
            for (int p = 0; p < 4; p++) {
                lo[p] = st[(kb + p) * 33 + n_local] * inv;
                hi[p] = st[(kb + 4 + p) * 33 + n_local] * inv;
            }
            const int fb = (sstep * 4 + rot4) & 15;
            float* o = g_Wt + (size_t)n * FDIM + c * 32 + fb * 2;
            *(float4*)o       = make_float4(lo[0], hi[0], lo[1], hi[1]);
            *(float4*)(o + 4) = make_float4(lo[2], hi[2], lo[3], hi[3]);
        }
    }
}

// ---------------------------------------------------------------------------
// Main: tf32 mma.sync GEMM 256x160x512, 16 warps (4x4), warp tile 64x40,
// cp.async 3-stage pipeline, fused tree-routing epilogue (two 128-row passes).
// ---------------------------------------------------------------------------
__global__ __launch_bounds__(NTHR, 1)
void detree_mma_kernel(const float* __restrict__ thr,
                       const float* __restrict__ logt,
                       const float* __restrict__ resp,
                       float* __restrict__ out) {
    extern __shared__ char sm[];
    float* s_resp = (float*)(sm + OFF_RESP);
    float* s_thr  = (float*)(sm + OFF_THR);
    float* s_it   = (float*)(sm + OFF_IT);
    float* s_D    = (float*)sm;
    const uint32_t smb = smem_u32(sm);

    const int tid  = threadIdx.x;
    const int wid  = tid >> 5;
    const int lane = tid & 31;
    const int g    = lane >> 2;
    const int tig  = lane & 3;
    const int wm   = wid >> 2;        // 0..3 -> rows wm*64..
    const int wn   = wid & 3;         // 0..3 -> cols wn*40..
    const int m0    = blockIdx.y * BM;
    const int tree0 = blockIdx.x * TB;
    const int n0    = tree0 * TDEPTH;

    if (tid < 256)
        ((float4*)s_resp)[tid] = ((const float4*)(resp + (size_t)tree0 * NLEAF))[tid];
    if (tid >= 256 && tid < 256 + TB * TDEPTH) {
        int q = tid - 256;
        s_thr[q] = thr[n0 + q];
        s_it[q]  = __expf(-logt[n0 + q]);
    }

    const float* aSrcBase = g_Xp + (size_t)m0 * FDIM;
    const float* bSrcBase = g_Wt + (size_t)n0 * FDIM;

    auto issue_chunk = [&](int i, int st) {
        const uint32_t aB = smb + st * STAGE_BYTES;
        const uint32_t bB = aB + 32768;
        const float* aS = aSrcBase + i * KC;
        const float* bS = bSrcBase + i * KC;
        #pragma unroll
        for (int r = 0; r < 4; r++) {          // A: 2048 quads
            int id = tid + r * NTHR;
            int row = id >> 3, q = id & 7;
            cpa16(aB + row * 128 + q * 16, aS + (size_t)row * FDIM + q * 4);
        }
        #pragma unroll
        for (int r = 0; r < 2; r++) {          // B: first 1024 quads
            int id = tid + r * NTHR;
            int row = id >> 3, q = id & 7;
            cpa16(bB + row * 128 + q * 16, bS + (size_t)row * FDIM + q * 4);
        }
        if (tid < 256) {                        // B: remaining 256 quads
            int id = 1024 + tid;
            int row = id >> 3, q = id & 7;
            cpa16(bB + row * 128 + q * 16, bS + (size_t)row * FDIM + q * 4);
        }
        CP_COMMIT();
    };

    float d[4][5][4];
    #pragma unroll
    for (int mt = 0; mt < 4; mt++)
        #pragma unroll
        for (int nt = 0; nt < 5; nt++)
            #pragma unroll
            for (int q = 0; q < 4; q++) d[mt][nt][q] = 0.f;

    issue_chunk(0, 0);
    issue_chunk(1, 1);

    for (int i = 0; i < NCHUNK; i++) {
        const int st = i % NSTAGE;
        if (i < NCHUNK - 1)
            asm volatile("cp.async.wait_group 1;" ::: "memory");
        else
            asm volatile("cp.async.wait_group 0;" ::: "memory");
        __syncthreads();
        if (i + 2 < NCHUNK) issue_chunk(i + 2, (i + 2) % NSTAGE);

        const uint32_t* As = (const uint32_t*)(sm + st * STAGE_BYTES);
        const uint32_t* Bs = (const uint32_t*)(sm + st * STAGE_BYTES + 32768);

        #pragma unroll
        for (int s = 0; s < 4; s++) {
            const int fb = ((s * 4 + tig) + 4 * (g & 3)) & 15;
            uint2 afLo[4], afHi[4], bf[5];
            #pragma unroll
            for (int mt = 0; mt < 4; mt++) {
                int row = wm * 64 + mt * 16 + g;
                afLo[mt] = *((const uint2*)(As + row * 32) + fb);
                afHi[mt] = *((const uint2*)(As + (row + 8) * 32) + fb);
            }
            #pragma unroll
            for (int nt = 0; nt < 5; nt++) {
                int row = wn * 40 + nt * 8 + g;
                bf[nt] = *((const uint2*)(Bs + row * 32) + fb);
            }
            #pragma unroll
            for (int mt = 0; mt < 4; mt++)
                #pragma unroll
                for (int nt = 0; nt < 5; nt++)
                    mma8(d[mt][nt], afLo[mt], afHi[mt], bf[nt]);
        }
    }
    __syncthreads();

    // ---- epilogue: two passes of 128 rows through s_D [128][162] ----
    #pragma unroll
    for (int h = 0; h < 2; h++) {
        if ((wm >> 1) == h) {
            const int rbase = (wm & 1) * 64;
            #pragma unroll
            for (int mt = 0; mt < 4; mt++) {
                const int row0 = rbase + mt * 16 + g;
                #pragma unroll
                for (int nt = 0; nt < 5; nt++) {
                    const int col = wn * 40 + nt * 8 + 2 * tig;
                    *(float2*)&s_D[row0 * 162 + col] =
                        make_float2(d[mt][nt][0], d[mt][nt][1]);
                    *(float2*)&s_D[(row0 + 8) * 162 + col] =
                        make_float2(d[mt][nt][2], d[mt][nt][3]);
                }
            }
        }
        __syncthreads();

        #pragma unroll
        for (int t = 0; t < 8; t++) {
            const int q   = tid + t * NTHR;
            const int row = q >> 5;
            const int tr  = q & 31;

            float c0a[5], c1a[5];
            #pragma unroll
            for (int dd = 0; dd < TDEPTH; dd++) {
                float fv = s_D[row * 162 + tr * 5 + dd];
                float tl = (fv - s_thr[tr * 5 + dd]) * s_it[tr * 5 + dd];
                c1a[dd] = __saturatef(fmaf( 0.5f, tl, 0.5f));
                c0a[dd] = __saturatef(fmaf(-0.5f, tl, 0.5f));
            }
            float p[NLEAF];
            p[0] = c0a[0];
            p[1] = c1a[0];
            #pragma unroll
            for (int jj = 1; jj < TDEPTH; jj++) {
                const int sz = 1 << jj;
                #pragma unroll
                for (int l = 0; l < 16; l++) {
                    if (l < sz) {
                        p[l + sz] = p[l] * c1a[jj];
                        p[l]      = p[l] * c0a[jj];
                    }
                }
            }
            float ssum = 0.f;
            const float4* r4 = (const float4*)&s_resp[tr * NLEAF];
            #pragma unroll
            for (int qq = 0; qq < 8; qq++) {
                float4 rv = r4[qq];
                ssum = fmaf(p[4 * qq + 0], rv.x, ssum);
                ssum = fmaf(p[4 * qq + 1], rv.y, ssum);
                ssum = fmaf(p[4 * qq + 2], rv.z, ssum);
                ssum = fmaf(p[4 * qq + 3], rv.w, ssum);
            }
            out[(size_t)(m0 + h * 128 + row) * NTREES + tree0 + tr] = ssum;
        }
        __syncthreads();
    }
}

extern "C" void kernel_launch(void* const* d_in, const int* in_sizes, int n_in,
                              void* d_out, int out_size) {
    const float* x    = (const float*)d_in[0];
    const float* fa   = (const float*)d_in[1];
    const float* thr  = (const float*)d_in[2];
    const float* logt = (const float*)d_in[3];
    const float* resp = (const float*)d_in[4];
    float* out = (float*)d_out;

    const int sm_soft = 512 * 33 * 4;
    cudaFuncSetAttribute(softmax_t_kernel,
                         cudaFuncAttributeMaxDynamicSharedMemorySize, sm_soft);
    cudaFuncSetAttribute(detree_mma_kernel,
                         cudaFuncAttributeMaxDynamicSharedMemorySize, SMEM_BYTES);

    // one thread per 8-float cell: BATCH*FDIM/8 threads total
    permute_x_kernel<<<(BATCH * FDIM / 8) / 256, 256>>>(x);
    softmax_t_kernel<<<NCOLS / 32, 256, sm_soft>>>(fa);
    detree_mma_kernel<<<dim3(NTREES / TB, BATCH / BM), NTHR, SMEM_BYTES>>>(
        thr, logt, resp, out);
}

// round 7
// speedup vs baseline: 1.8702x; 1.5089x over previous
#include <cuda_runtime.h>
#include <cuda_fp16.h>
#include <cstdint>

#define BATCH   2048
#define FDIM    512
#define NTREES  512
#define NCOLS   2560
#define TDEPTH  5
#define NLEAF   32

#define BM      256      // batch rows per CTA
#define TB      32       // trees per CTA
#define BN      160      // GEMM N per CTA
#define KC      64       // K per chunk (64 fp16 = 128B rows)
#define NCHUNK  8        // 512/64
#define NTHR    512      // 16 warps, 4x4, warp tile 64x40
#define NSTAGE  3

// pre-permuted fp16 operands (slot-interleaved, row-rotated)
__device__ __half g_Xh[BATCH * FDIM];        // 2 MB
__device__ __half g_Wh[NCOLS * FDIM];        // 2.5 MB

// smem: 3 stages x (A 256x128B = 32KB + B 160x128B = 20KB) then tables
#define STAGE_BYTES 53248
#define OFF_TAB     (NSTAGE * STAGE_BYTES)          // 159744
#define OFF_RESP    OFF_TAB
#define OFF_THR     (OFF_TAB + 4096)
#define OFF_IT      (OFF_TAB + 4736)
#define SMEM_BYTES  (OFF_TAB + 5376)

// Slot layout per 128B row (16 slots of 8B): for k16-step s (0..3), slot
// (s*4 + j + 4*(row&3)) & 15 holds halves [k(2j), k(2j+1), k(2j+8), k(2j+9)]
// of that step (k local to the step). Load side: thread (g,tig) reads slot
// ((s*4+tig) + 4*(g&3)) & 15  ->  {a-lo-pair, a-hi-pair} / {b0, b1}.

__device__ __forceinline__ uint32_t smem_u32(const void* p) {
    uint32_t a;
    asm("{ .reg .u64 t; cvta.to.shared.u64 t, %1; cvt.u32.u64 %0, t; }"
        : "=r"(a) : "l"(p));
    return a;
}
__device__ __forceinline__ void cpa16(uint32_t dst, const void* src) {
    asm volatile("cp.async.cg.shared.global [%0], [%1], 16;"
                 :: "r"(dst), "l"(src));
}
#define CP_COMMIT() asm volatile("cp.async.commit_group;" ::: "memory")

// m16n8k16 f16 -> f32
__device__ __forceinline__ void mma16(float* d, uint2 aP, uint2 aQ, uint2 b) {
    // aP = {a0,a2} (row g), aQ = {a1,a3} (row g+8), b = {b0,b1}
    asm volatile(
        "mma.sync.aligned.m16n8k16.row.col.f32.f16.f16.f32 "
        "{%0,%1,%2,%3}, {%4,%5,%6,%7}, {%8,%9}, {%0,%1,%2,%3};"
        : "+f"(d[0]), "+f"(d[1]), "+f"(d[2]), "+f"(d[3])
        : "r"(aP.x), "r"(aQ.x), "r"(aP.y), "r"(aQ.y), "r"(b.x), "r"(b.y));
}

// pack 16 floats (one k16 step) into 4 slots at dst (32B, 16B-aligned)
__device__ __forceinline__ void pack16(__half* dst, const float* h) {
    uint32_t w[8];
    #pragma unroll
    for (int j = 0; j < 4; j++) {
        __half2 lo = __floats2half2_rn(h[2 * j],     h[2 * j + 1]);
        __half2 hi = __floats2half2_rn(h[2 * j + 8], h[2 * j + 9]);
        w[2 * j]     = *(uint32_t*)&lo;
        w[2 * j + 1] = *(uint32_t*)&hi;
    }
    *(uint4*)dst       = make_uint4(w[0], w[1], w[2], w[3]);
    *(uint4*)(dst + 8) = make_uint4(w[4], w[5], w[6], w[7]);
}

// ---------------------------------------------------------------------------
// Fused prep: blocks [0,80) = softmax+permute W ; blocks [80,336) = permute X
// ---------------------------------------------------------------------------
__global__ void prep_kernel(const float* __restrict__ fa,
                            const float* __restrict__ x) {
    extern __shared__ float st[];              // [512][33] (softmax path only)
    const int tid = threadIdx.x;

    if (blockIdx.x >= 80) {
        // ---- permute X: one k16 cell per thread (65536 cells) ----
        const int id  = (blockIdx.x - 80) * 256 + tid;
        const int row = id >> 5;               // 32 cells per row
        const int c   = (id >> 2) & 7;         // chunk (KC=64)
        const int s   = id & 3;                // k16 step
        float h[16];
        const float* src = x + (size_t)row * FDIM + c * 64 + s * 16;
        #pragma unroll
        for (int q = 0; q < 4; q++) {
            float4 v = *(const float4*)(src + q * 4);
            h[q * 4 + 0] = v.x; h[q * 4 + 1] = v.y;
            h[q * 4 + 2] = v.z; h[q * 4 + 3] = v.w;
        }
        const int fb = (s * 4 + 4 * (row & 3)) & 15;
        pack16(g_Xh + (size_t)row * FDIM + c * 64 + fb * 4, h);
        return;
    }

    // ---- softmax over axis 0 for 32 columns, then transposed fp16 write ----
    __shared__ float red[8][32];
    __shared__ float s_mx[32], s_inv[32];
    const int lx = tid & 31;
    const int ry = tid >> 5;
    const int c0 = blockIdx.x * 32;

    #pragma unroll
    for (int r = 0; r < 16; r++) {
        int q = tid + r * 256;
        int f = q >> 3, cq = q & 7;
        float4 v = *(const float4*)&fa[(size_t)f * NCOLS + c0 + cq * 4];
        float* p = &st[f * 33 + cq * 4];
        p[0] = v.x; p[1] = v.y; p[2] = v.z; p[3] = v.w;
    }
    __syncthreads();

    float m = -1e30f;
    for (int f = ry; f < FDIM; f += 8) m = fmaxf(m, st[f * 33 + lx]);
    red[ry][lx] = m;
    __syncthreads();
    if (ry == 0) {
        float mm = red[0][lx];
        #pragma unroll
        for (int r = 1; r < 8; r++) mm = fmaxf(mm, red[r][lx]);
        s_mx[lx] = mm;
    }
    __syncthreads();
    const float mx = s_mx[lx];

    float s = 0.f;
    for (int f = ry; f < FDIM; f += 8) {
        float e = __expf(st[f * 33 + lx] - mx);
        st[f * 33 + lx] = e;
        s += e;
    }
    red[ry][lx] = s;
    __syncthreads();
    if (ry == 0) {
        float t = 0.f;
        #pragma unroll
        for (int r = 0; r < 8; r++) t += red[r][lx];
        s_inv[lx] = 1.0f / t;
    }
    __syncthreads();

    // warp w handles chunk w; lane = column (conflict-free st reads)
    const int c       = tid >> 5;               // chunk 0..7
    const int n_local = tid & 31;
    const int n       = c0 + n_local;
    const float inv   = s_inv[n_local];
    const int rot4    = 4 * (n_local & 3);

    #pragma unroll
    for (int sstep = 0; sstep < 4; sstep++) {
        const int kb = c * 64 + sstep * 16;
        float h[16];
        #pragma unroll
        for (int p = 0; p < 16; p++)
            h[p] = st[(kb + p) * 33 + n_local] * inv;
        const int fb = (sstep * 4 + rot4) & 15;
        pack16(g_Wh + (size_t)n * FDIM + c * 64 + fb * 4, h);
    }
}

// ---------------------------------------------------------------------------
// Main: fp16 mma.sync m16n8k16 GEMM 256x160x512, 16 warps (4x4), warp 64x40,
// cp.async 3-stage pipeline, fused tree-routing epilogue (two 128-row passes).
// ---------------------------------------------------------------------------
__global__ __launch_bounds__(NTHR, 1)
void detree_mma_kernel(const float* __restrict__ thr,
                       const float* __restrict__ logt,
                       const float* __restrict__ resp,
                       float* __restrict__ out) {
    extern __shared__ char sm[];
    float* s_resp = (float*)(sm + OFF_RESP);
    float* s_thr  = (float*)(sm + OFF_THR);
    float* s_it   = (float*)(sm + OFF_IT);
    float* s_D    = (float*)sm;
    const uint32_t smb = smem_u32(sm);

    const int tid  = threadIdx.x;
    const int wid  = tid >> 5;
    const int lane = tid & 31;
    const int g    = lane >> 2;
    const int tig  = lane & 3;
    const int wm   = wid >> 2;
    const int wn   = wid & 3;
    const int m0    = blockIdx.y * BM;
    const int tree0 = blockIdx.x * TB;
    const int n0    = tree0 * TDEPTH;

    if (tid < 256)
        ((float4*)s_resp)[tid] = ((const float4*)(resp + (size_t)tree0 * NLEAF))[tid];
    if (tid >= 256 && tid < 256 + TB * TDEPTH) {
        int q = tid - 256;
        s_thr[q] = thr[n0 + q];
        s_it[q]  = __expf(-logt[n0 + q]);
    }

    const __half* aSrcBase = g_Xh + (size_t)m0 * FDIM;
    const __half* bSrcBase = g_Wh + (size_t)n0 * FDIM;

    auto issue_chunk = [&](int i, int st) {
        const uint32_t aB = smb + st * STAGE_BYTES;
        const uint32_t bB = aB + 32768;
        const __half* aS = aSrcBase + i * KC;
        const __half* bS = bSrcBase + i * KC;
        #pragma unroll
        for (int r = 0; r < 4; r++) {          // A: 2048 16B quads
            int id = tid + r * NTHR;
            int row = id >> 3, q = id & 7;
            cpa16(aB + row * 128 + q * 16, aS + (size_t)row * FDIM + q * 8);
        }
        #pragma unroll
        for (int r = 0; r < 2; r++) {          // B: first 1024 quads
            int id = tid + r * NTHR;
            int row = id >> 3, q = id & 7;
            cpa16(bB + row * 128 + q * 16, bS + (size_t)row * FDIM + q * 8);
        }
        if (tid < 256) {                        // B: remaining 256 quads
            int id = 1024 + tid;
            int row = id >> 3, q = id & 7;
            cpa16(bB + row * 128 + q * 16, bS + (size_t)row * FDIM + q * 8);
        }
        CP_COMMIT();
    };

    float d[4][5][4];
    #pragma unroll
    for (int mt = 0; mt < 4; mt++)
        #pragma unroll
        for (int nt = 0; nt < 5; nt++)
            #pragma unroll
            for (int q = 0; q < 4; q++) d[mt][nt][q] = 0.f;

    issue_chunk(0, 0);
    issue_chunk(1, 1);

    for (int i = 0; i < NCHUNK; i++) {
        const int st = i % NSTAGE;
        if (i < NCHUNK - 1)
            asm volatile("cp.async.wait_group 1;" ::: "memory");
        else
            asm volatile("cp.async.wait_group 0;" ::: "memory");
        __syncthreads();
        if (i + 2 < NCHUNK) issue_chunk(i + 2, (i + 2) % NSTAGE);

        const uint32_t* As = (const uint32_t*)(sm + st * STAGE_BYTES);
        const uint32_t* Bs = (const uint32_t*)(sm + st * STAGE_BYTES + 32768);

        #pragma unroll
        for (int s = 0; s < 4; s++) {
            const int fb = ((s * 4 + tig) + 4 * (g & 3)) & 15;
            uint2 aP[4], aQ[4], bf[5];
            #pragma unroll
            for (int mt = 0; mt < 4; mt++) {
                int row = wm * 64 + mt * 16 + g;
                aP[mt] = *((const uint2*)(As + row * 32) + fb);        // row g
                aQ[mt] = *((const uint2*)(As + (row + 8) * 32) + fb);  // row g+8
            }
            #pragma unroll
            for (int nt = 0; nt < 5; nt++) {
                int row = wn * 40 + nt * 8 + g;
                bf[nt] = *((const uint2*)(Bs + row * 32) + fb);
            }
            #pragma unroll
            for (int mt = 0; mt < 4; mt++)
                #pragma unroll
                for (int nt = 0; nt < 5; nt++)
                    mma16(d[mt][nt], aP[mt], aQ[mt], bf[nt]);
        }
    }
    __syncthreads();

    // ---- epilogue: two passes of 128 rows through s_D [128][162] ----
    #pragma unroll
    for (int h = 0; h < 2; h++) {
        if ((wm >> 1) == h) {
            const int rbase = (wm & 1) * 64;
            #pragma unroll
            for (int mt = 0; mt < 4; mt++) {
                const int row0 = rbase + mt * 16 + g;
                #pragma unroll
                for (int nt = 0; nt < 5; nt++) {
                    const int col = wn * 40 + nt * 8 + 2 * tig;
                    *(float2*)&s_D[row0 * 162 + col] =
                        make_float2(d[mt][nt][0], d[mt][nt][1]);
                    *(float2*)&s_D[(row0 + 8) * 162 + col] =
                        make_float2(d[mt][nt][2], d[mt][nt][3]);
                }
            }
        }
        __syncthreads();

        #pragma unroll
        for (int t = 0; t < 8; t++) {
            const int q   = tid + t * NTHR;
            const int row = q >> 5;
            const int tr  = q & 31;

            float c0a[5], c1a[5];
            #pragma unroll
            for (int dd = 0; dd < TDEPTH; dd++) {
                float fv = s_D[row * 162 + tr * 5 + dd];
                float tl = (fv - s_thr[tr * 5 + dd]) * s_it[tr * 5 + dd];
                c1a[dd] = __saturatef(fmaf( 0.5f, tl, 0.5f));
                c0a[dd] = __saturatef(fmaf(-0.5f, tl, 0.5f));
            }
            float p[NLEAF];
            p[0] = c0a[0];
            p[1] = c1a[0];
            #pragma unroll
            for (int jj = 1; jj < TDEPTH; jj++) {
                const int sz = 1 << jj;
                #pragma unroll
                for (int l = 0; l < 16; l++) {
                    if (l < sz) {
                        p[l + sz] = p[l] * c1a[jj];
                        p[l]      = p[l] * c0a[jj];
                    }
                }
            }
            float ssum = 0.f;
            const float4* r4 = (const float4*)&s_resp[tr * NLEAF];
            #pragma unroll
            for (int qq = 0; qq < 8; qq++) {
                float4 rv = r4[qq];
                ssum = fmaf(p[4 * qq + 0], rv.x, ssum);
                ssum = fmaf(p[4 * qq + 1], rv.y, ssum);
                ssum = fmaf(p[4 * qq + 2], rv.z, ssum);
                ssum = fmaf(p[4 * qq + 3], rv.w, ssum);
            }
            out[(size_t)(m0 + h * 128 + row) * NTREES + tree0 + tr] = ssum;
        }
        __syncthreads();
    }
}

extern "C" void kernel_launch(void* const* d_in, const int* in_sizes, int n_in,
                              void* d_out, int out_size) {
    const float* x    = (const float*)d_in[0];
    const float* fa   = (const float*)d_in[1];
    const float* thr  = (const float*)d_in[2];
    const float* logt = (const float*)d_in[3];
    const float* resp = (const float*)d_in[4];
    float* out = (float*)d_out;

    const int sm_prep = 512 * 33 * 4;
    cudaFuncSetAttribute(prep_kernel,
                         cudaFuncAttributeMaxDynamicSharedMemorySize, sm_prep);
    cudaFuncSetAttribute(detree_mma_kernel,
                         cudaFuncAttributeMaxDynamicSharedMemorySize, SMEM_BYTES);

    // 80 softmax blocks + 256 x-permute blocks in one launch
    prep_kernel<<<80 + 256, 256, sm_prep>>>(fa, x);
    detree_mma_kernel<<<dim3(NTREES / TB, BATCH / BM), NTHR, SMEM_BYTES>>>(
        thr, logt, resp, out);
}

// round 8
// speedup vs baseline: 2.2128x; 1.1832x over previous
#include <cuda_runtime.h>
#include <cuda_fp16.h>
#include <cstdint>

#define BATCH   2048
#define FDIM    512
#define NTREES  512
#define NCOLS   2560
#define TDEPTH  5
#define NLEAF   32

#define BM      256
#define TB      32
#define BN      160
#define KC      64       // 64 fp16 = 128B rows
#define NCHUNK  8
#define NTHR    512      // 16 warps, 4x4, warp tile 64x40
#define NSTAGE  3

__device__ __half g_Xh[BATCH * FDIM];
__device__ __half g_Wh[NCOLS * FDIM];

// smem: 3 stages x (A 256x128B + B 160x128B) = 159744; s_D [256][162] f32
// reuses [0,165888); tables above.
#define STAGE_BYTES 53248
#define OFF_RESP    165888                     // 32 trees x stride 36 floats
#define OFF_THR     (OFF_RESP + 4608)
#define OFF_IT      (OFF_THR + 640)
#define SMEM_BYTES  (OFF_IT + 640)

__device__ __forceinline__ uint32_t smem_u32(const void* p) {
    uint32_t a;
    asm("{ .reg .u64 t; cvta.to.shared.u64 t, %1; cvt.u32.u64 %0, t; }"
        : "=r"(a) : "l"(p));
    return a;
}
__device__ __forceinline__ void cpa16(uint32_t dst, const void* src) {
    asm volatile("cp.async.cg.shared.global [%0], [%1], 16;"
                 :: "r"(dst), "l"(src));
}
#define CP_COMMIT() asm volatile("cp.async.commit_group;" ::: "memory")

__device__ __forceinline__ void mma16(float* d, uint2 aP, uint2 aQ, uint2 b) {
    asm volatile(
        "mma.sync.aligned.m16n8k16.row.col.f32.f16.f16.f32 "
        "{%0,%1,%2,%3}, {%4,%5,%6,%7}, {%8,%9}, {%0,%1,%2,%3};"
        : "+f"(d[0]), "+f"(d[1]), "+f"(d[2]), "+f"(d[3])
        : "r"(aP.x), "r"(aQ.x), "r"(aP.y), "r"(aQ.y), "r"(b.x), "r"(b.y));
}

__device__ __forceinline__ void pack16(__half* dst, const float* h) {
    uint32_t w[8];
    #pragma unroll
    for (int j = 0; j < 4; j++) {
        __half2 lo = __floats2half2_rn(h[2 * j],     h[2 * j + 1]);
        __half2 hi = __floats2half2_rn(h[2 * j + 8], h[2 * j + 9]);
        w[2 * j]     = *(uint32_t*)&lo;
        w[2 * j + 1] = *(uint32_t*)&hi;
    }
    *(uint4*)dst       = make_uint4(w[0], w[1], w[2], w[3]);
    *(uint4*)(dst + 8) = make_uint4(w[4], w[5], w[6], w[7]);
}

// ---------------------------------------------------------------------------
// Fused prep: blocks [0,80) = softmax+permute W ; blocks [80,208) = permute X
// X path: 2 cells per thread (batched loads -> batched stores) for MLP.
// ---------------------------------------------------------------------------
__global__ void prep_kernel(const float* __restrict__ fa,
                            const float* __restrict__ x) {
    extern __shared__ float st[];
    const int tid = threadIdx.x;

    if (blockIdx.x >= 80) {
        const int base = (blockIdx.x - 80) * 512 + tid;   // 2 cells, stride 256
        float h[2][16];
        int fbo[2];
        #pragma unroll
        for (int u = 0; u < 2; u++) {
            const int id  = base + u * 256;
            const int row = id >> 5;
            const int c   = (id >> 2) & 7;
            const int s   = id & 3;
            const float* src = x + (size_t)row * FDIM + c * 64 + s * 16;
            #pragma unroll
            for (int q = 0; q < 4; q++) {
                float4 v = *(const float4*)(src + q * 4);
                h[u][q * 4 + 0] = v.x; h[u][q * 4 + 1] = v.y;
                h[u][q * 4 + 2] = v.z; h[u][q * 4 + 3] = v.w;
            }
            const int fb = (s * 4 + 4 * (row & 3)) & 15;
            fbo[u] = row * FDIM + c * 64 + fb * 4;
        }
        #pragma unroll
        for (int u = 0; u < 2; u++)
            pack16(g_Xh + (size_t)fbo[u], h[u]);
        return;
    }

    __shared__ float red[8][32];
    __shared__ float s_mx[32], s_inv[32];
    const int lx = tid & 31;
    const int ry = tid >> 5;
    const int c0 = blockIdx.x * 32;

    #pragma unroll
    for (int r = 0; r < 16; r++) {
        int q = tid + r * 256;
        int f = q >> 3, cq = q & 7;
        float4 v = *(const float4*)&fa[(size_t)f * NCOLS + c0 + cq * 4];
        float* p = &st[f * 33 + cq * 4];
        p[0] = v.x; p[1] = v.y; p[2] = v.z; p[3] = v.w;
    }
    __syncthreads();

    float m = -1e30f;
    for (int f = ry; f < FDIM; f += 8) m = fmaxf(m, st[f * 33 + lx]);
    red[ry][lx] = m;
    __syncthreads();
    if (ry == 0) {
        float mm = red[0][lx];
        #pragma unroll
        for (int r = 1; r < 8; r++) mm = fmaxf(mm, red[r][lx]);
        s_mx[lx] = mm;
    }
    __syncthreads();
    const float mx = s_mx[lx];

    float s = 0.f;
    for (int f = ry; f < FDIM; f += 8) {
        float e = __expf(st[f * 33 + lx] - mx);
        st[f * 33 + lx] = e;
        s += e;
    }
    red[ry][lx] = s;
    __syncthreads();
    if (ry == 0) {
        float t = 0.f;
        #pragma unroll
        for (int r = 0; r < 8; r++) t += red[r][lx];
        s_inv[lx] = 1.0f / t;
    }
    __syncthreads();

    const int c       = tid >> 5;
    const int n_local = tid & 31;
    const int n       = c0 + n_local;
    const float inv   = s_inv[n_local];
    const int rot4    = 4 * (n_local & 3);

    #pragma unroll
    for (int sstep = 0; sstep < 4; sstep++) {
        const int kb = c * 64 + sstep * 16;
        float h[16];
        #pragma unroll
        for (int p = 0; p < 16; p++)
            h[p] = st[(kb + p) * 33 + n_local] * inv;
        const int fb = (sstep * 4 + rot4) & 15;
        pack16(g_Wh + (size_t)n * FDIM + c * 64 + fb * 4, h);
    }
}

// ---------------------------------------------------------------------------
// Main: fp16 m16n8k16 GEMM 256x160x512 + single-pass fused tree epilogue.
// ---------------------------------------------------------------------------
__global__ __launch_bounds__(NTHR, 1)
void detree_mma_kernel(const float* __restrict__ thr,
                       const float* __restrict__ logt,
                       const float* __restrict__ resp,
                       float* __restrict__ out) {
    extern __shared__ char sm[];
    float* s_resp = (float*)(sm + OFF_RESP);   // [32][36] padded
    float* s_thr  = (float*)(sm + OFF_THR);
    float* s_it   = (float*)(sm + OFF_IT);
    float* s_D    = (float*)sm;                // [256][162]
    const uint32_t smb = smem_u32(sm);

    const int tid  = threadIdx.x;
    const int lane = tid & 31;
    const int wid  = tid >> 5;
    const int g    = lane >> 2;
    const int tig  = lane & 3;
    const int wm   = wid >> 2;
    const int wn   = wid & 3;
    const int m0    = blockIdx.y * BM;
    const int tree0 = blockIdx.x * TB;
    const int n0    = tree0 * TDEPTH;

    if (tid < 256) {                           // response, bank-padded stride 36
        int t = tid >> 3, l4 = (tid & 7) * 4;
        *(float4*)&s_resp[t * 36 + l4] =
            *(const float4*)&resp[(size_t)(tree0 + t) * NLEAF + l4];
    }
    if (tid >= 256 && tid < 256 + TB * TDEPTH) {
        int q = tid - 256;
        s_thr[q] = thr[n0 + q];
        s_it[q]  = __expf(-logt[n0 + q]);
    }

    // hoisted invariants
    int fb8[4];
    #pragma unroll
    for (int s = 0; s < 4; s++)
        fb8[s] = (((s * 4 + tig) + 4 * (g & 3)) & 15) * 8;
    int aoff[4], boff[5];
    #pragma unroll
    for (int mt = 0; mt < 4; mt++) aoff[mt] = (wm * 64 + mt * 16 + g) * 128;
    #pragma unroll
    for (int nt = 0; nt < 5; nt++) boff[nt] = 32768 + (wn * 40 + nt * 8 + g) * 128;

    const __half* aSrcBase = g_Xh + (size_t)m0 * FDIM;
    const __half* bSrcBase = g_Wh + (size_t)n0 * FDIM;

    auto issue_chunk = [&](int i, int st) {
        const uint32_t aB = smb + st * STAGE_BYTES;
        const uint32_t bB = aB + 32768;
        const __half* aS = aSrcBase + i * KC;
        const __half* bS = bSrcBase + i * KC;
        #pragma unroll
        for (int r = 0; r < 4; r++) {
            int id = tid + r * NTHR;
            int row = id >> 3, q = id & 7;
            cpa16(aB + row * 128 + q * 16, aS + (size_t)row * FDIM + q * 8);
        }
        #pragma unroll
        for (int r = 0; r < 2; r++) {
            int id = tid + r * NTHR;
            int row = id >> 3, q = id & 7;
            cpa16(bB + row * 128 + q * 16, bS + (size_t)row * FDIM + q * 8);
        }
        if (tid < 256) {
            int id = 1024 + tid;
            int row = id >> 3, q = id & 7;
            cpa16(bB + row * 128 + q * 16, bS + (size_t)row * FDIM + q * 8);
        }
        CP_COMMIT();
    };

    float d[4][5][4];
    #pragma unroll
    for (int mt = 0; mt < 4; mt++)
        #pragma unroll
        for (int nt = 0; nt < 5; nt++)
            #pragma unroll
            for (int q = 0; q < 4; q++) d[mt][nt][q] = 0.f;

    issue_chunk(0, 0);
    issue_chunk(1, 1);

    for (int i = 0; i < NCHUNK; i++) {
        const int st = i % NSTAGE;
        if (i < NCHUNK - 1)
            asm volatile("cp.async.wait_group 1;" ::: "memory");
        else
            asm volatile("cp.async.wait_group 0;" ::: "memory");
        __syncthreads();
        if (i + 2 < NCHUNK) issue_chunk(i + 2, (i + 2) % NSTAGE);

        const char* stB = sm + st * STAGE_BYTES;

        #pragma unroll
        for (int s = 0; s < 4; s++) {
            uint2 aP[4], aQ[4], bf[5];
            #pragma unroll
            for (int mt = 0; mt < 4; mt++) {
                const char* pa = stB + aoff[mt] + fb8[s];
                aP[mt] = *(const uint2*)pa;
                aQ[mt] = *(const uint2*)(pa + 1024);
            }
            #pragma unroll
            for (int nt = 0; nt < 5; nt++)
                bf[nt] = *(const uint2*)(stB + boff[nt] + fb8[s]);
            #pragma unroll
            for (int mt = 0; mt < 4; mt++)
                #pragma unroll
                for (int nt = 0; nt < 5; nt++)
                    mma16(d[mt][nt], aP[mt], aQ[mt], bf[nt]);
        }
    }
    __syncthreads();

    // ---- all D -> s_D [256][162] (single pass; accumulators die here) ----
    #pragma unroll
    for (int mt = 0; mt < 4; mt++) {
        const int row0 = wm * 64 + mt * 16 + g;
        #pragma unroll
        for (int nt = 0; nt < 5; nt++) {
            const int col = wn * 40 + nt * 8 + 2 * tig;
            *(float2*)&s_D[row0 * 162 + col] =
                make_float2(d[mt][nt][0], d[mt][nt][1]);
            *(float2*)&s_D[(row0 + 8) * 162 + col] =
                make_float2(d[mt][nt][2], d[mt][nt][3]);
        }
    }
    __syncthreads();

    // ---- epilogue: fixed tree per thread, register tables, backward
    //      contraction. 512 threads x 16 rows = 256 rows x 32 trees. ----
    const int tr = tid & 31;            // local tree
    const int rb = tid >> 5;            // row base 0..15

    float itv[5], thr_it[5];
    #pragma unroll
    for (int dd = 0; dd < TDEPTH; dd++) {
        itv[dd]    = s_it[tr * 5 + dd];
        thr_it[dd] = s_thr[tr * 5 + dd] * itv[dd];
    }
    float r[NLEAF];
    #pragma unroll
    for (int q = 0; q < 8; q++) {
        float4 v = *(const float4*)&s_resp[tr * 36 + q * 4];
        r[4 * q + 0] = v.x; r[4 * q + 1] = v.y;
        r[4 * q + 2] = v.z; r[4 * q + 3] = v.w;
    }

    #pragma unroll
    for (int t = 0; t < 16; t++) {
        const int row = rb + t * 16;
        float c0a[5], c1a[5];
        #pragma unroll
        for (int dd = 0; dd < TDEPTH; dd++) {
            float tl = fmaf(s_D[row * 162 + tr * 5 + dd], itv[dd], -thr_it[dd]);
            c1a[dd] = __saturatef(fmaf( 0.5f, tl, 0.5f));
            c0a[dd] = __saturatef(fmaf(-0.5f, tl, 0.5f));
        }
        // backward contraction over depth bits (leaf bit j selects c1a[j])
        float s4[16];
        #pragma unroll
        for (int i2 = 0; i2 < 16; i2++)
            s4[i2] = fmaf(c1a[4], r[i2 + 16], c0a[4] * r[i2]);
        float s3[8];
        #pragma unroll
        for (int i2 = 0; i2 < 8; i2++)
            s3[i2] = fmaf(c1a[3], s4[i2 + 8], c0a[3] * s4[i2]);
        float s2[4];
        #pragma unroll
        for (int i2 = 0; i2 < 4; i2++)
            s2[i2] = fmaf(c1a[2], s3[i2 + 4], c0a[2] * s3[i2]);
        float s1[2];
        #pragma unroll
        for (int i2 = 0; i2 < 2; i2++)
            s1[i2] = fmaf(c1a[1], s2[i2 + 2], c0a[1] * s2[i2]);
        float ssum = fmaf(c1a[0], s1[1], c0a[0] * s1[0]);

        out[(size_t)(m0 + row) * NTREES + tree0 + tr] = ssum;
    }
}

extern "C" void kernel_launch(void* const* d_in, const int* in_sizes, int n_in,
                              void* d_out, int out_size) {
    const float* x    = (const float*)d_in[0];
    const float* fa   = (const float*)d_in[1];
    const float* thr  = (const float*)d_in[2];
    const float* logt = (const float*)d_in[3];
    const float* resp = (const float*)d_in[4];
    float* out = (float*)d_out;

    const int sm_prep = 512 * 33 * 4;
    cudaFuncSetAttribute(prep_kernel,
                         cudaFuncAttributeMaxDynamicSharedMemorySize, sm_prep);
    cudaFuncSetAttribute(detree_mma_kernel,
                         cudaFuncAttributeMaxDynamicSharedMemorySize, SMEM_BYTES);

    // 80 softmax blocks + 128 x-permute blocks (2 cells/thread)
    prep_kernel<<<80 + 128, 256, sm_prep>>>(fa, x);
    detree_mma_kernel<<<dim3(NTREES / TB, BATCH / BM), NTHR, SMEM_BYTES>>>(
        thr, logt, resp, out);
}